// round 6
// baseline (speedup 1.0000x reference)
#include <cuda_runtime.h>

// ---------------- problem constants ----------------
#define NTOK   3600            // B*Q
#define NCOLS  32768           // G * TOTAL  (params row / out2 row width)
#define SPLITK 8
#define KCHUNK (NCOLS / SPLITK)   // 4096
#define LN_EPS 1e-5f

// ---------------- scratch (device globals; no allocations allowed) -------
__device__ float g_params[(size_t)NTOK * NCOLS];          // 472 MB
__device__ float g_out2[(size_t)NTOK * NCOLS];            // 472 MB
__device__ float g_part[(size_t)SPLITK * NTOK * 256];     // 29.5 MB

// =====================================================================
// SGEMM: C[M,N] = A[M,K] @ B[K,N] (+ bias over N)
// 128x128 block tile, BK=8, 256 threads, 8x8 per-thread microtile.
// kChunk > 0: split-K mode -> each blockIdx.z computes partial over its
// K-chunk and writes to C + z*M*N (no bias).
// =====================================================================
__global__ __launch_bounds__(256, 2)
void sgemm128(const float* __restrict__ A, const float* __restrict__ B,
              const float* __restrict__ bias, float* __restrict__ C,
              int M, int N, int K, int kChunk)
{
    __shared__ float As[8][132];   // +4 pad: conflict-free transposed stores
    __shared__ float Bs[8][128];

    const int tid  = threadIdx.x;
    const int brow = blockIdx.y * 128;
    const int bcol = blockIdx.x * 128;

    int kStart = 0, kEnd = K;
    float* Cp = C;
    if (kChunk > 0) {
        kStart = blockIdx.z * kChunk;
        kEnd   = kStart + kChunk;
        Cp     = C + (size_t)blockIdx.z * (size_t)M * (size_t)N;
    }

    const int trow = (tid >> 4) * 8;       // 0..120
    const int tcol = (tid & 15) * 8;       // 0..120
    const int aRow = tid >> 1;             // 0..127
    const int aCol = (tid & 1) * 4;        // 0 or 4
    const int bRow = tid >> 5;             // 0..7
    const int bCol = (tid & 31) * 4;       // 0..124

    float acc[8][8];
    #pragma unroll
    for (int i = 0; i < 8; i++)
        #pragma unroll
        for (int j = 0; j < 8; j++) acc[i][j] = 0.f;

    const int gr = brow + aRow;
    const float* Aptr = A + (size_t)gr * (size_t)K;

    for (int k0 = kStart; k0 < kEnd; k0 += 8) {
        // load A tile (transpose into As), guard M boundary
        float4 av = make_float4(0.f, 0.f, 0.f, 0.f);
        if (gr < M)
            av = *reinterpret_cast<const float4*>(Aptr + k0 + aCol);
        As[aCol + 0][aRow] = av.x;
        As[aCol + 1][aRow] = av.y;
        As[aCol + 2][aRow] = av.z;
        As[aCol + 3][aRow] = av.w;
        // load B tile (N is always a multiple of 128 here)
        *reinterpret_cast<float4*>(&Bs[bRow][bCol]) =
            *reinterpret_cast<const float4*>(B + (size_t)(k0 + bRow) * (size_t)N + bcol + bCol);
        __syncthreads();

        #pragma unroll
        for (int kk = 0; kk < 8; kk++) {
            float ra[8], rb[8];
            *reinterpret_cast<float4*>(&ra[0]) = *reinterpret_cast<const float4*>(&As[kk][trow]);
            *reinterpret_cast<float4*>(&ra[4]) = *reinterpret_cast<const float4*>(&As[kk][trow + 4]);
            *reinterpret_cast<float4*>(&rb[0]) = *reinterpret_cast<const float4*>(&Bs[kk][tcol]);
            *reinterpret_cast<float4*>(&rb[4]) = *reinterpret_cast<const float4*>(&Bs[kk][tcol + 4]);
            #pragma unroll
            for (int i = 0; i < 8; i++)
                #pragma unroll
                for (int j = 0; j < 8; j++)
                    acc[i][j] = fmaf(ra[i], rb[j], acc[i][j]);
        }
        __syncthreads();
    }

    #pragma unroll
    for (int i = 0; i < 8; i++) {
        int r = brow + trow + i;
        if (r < M) {
            #pragma unroll
            for (int j = 0; j < 8; j += 4) {
                int c = bcol + tcol + j;
                float4 v;
                v.x = acc[i][j];     v.y = acc[i][j + 1];
                v.z = acc[i][j + 2]; v.w = acc[i][j + 3];
                if (bias) {
                    v.x += bias[c];     v.y += bias[c + 1];
                    v.z += bias[c + 2]; v.w += bias[c + 3];
                }
                *reinterpret_cast<float4*>(Cp + (size_t)r * (size_t)N + c) = v;
            }
        }
    }
}

// =====================================================================
// block-wide (sum, sumsq) reduction, 256 threads
// =====================================================================
__device__ __forceinline__ float2 block_reduce2(float s, float q, float* red)
{
    #pragma unroll
    for (int off = 16; off > 0; off >>= 1) {
        s += __shfl_down_sync(0xffffffffu, s, off);
        q += __shfl_down_sync(0xffffffffu, q, off);
    }
    const int w = threadIdx.x >> 5;
    if ((threadIdx.x & 31) == 0) { red[w] = s; red[8 + w] = q; }
    __syncthreads();
    if (threadIdx.x < 32) {
        s = (threadIdx.x < 8) ? red[threadIdx.x]     : 0.f;
        q = (threadIdx.x < 8) ? red[8 + threadIdx.x] : 0.f;
        #pragma unroll
        for (int off = 4; off > 0; off >>= 1) {
            s += __shfl_down_sync(0xffffffffu, s, off);
            q += __shfl_down_sync(0xffffffffu, q, off);
        }
        if (threadIdx.x == 0) { red[0] = s; red[1] = q; }
    }
    __syncthreads();
    return make_float2(red[0], red[1]);
}

// =====================================================================
// Fused per-(token,group) kernel:
//   out1 = relu(LN2d( x[n,g] (32x64) @ M[n,g] (64x64) ))      [in SMEM]
//   out2 = relu(LN2d( S[n,g] (128x32) @ out1 (32x64) ))       -> global
// One block per (n,g). 256 threads.
// =====================================================================
__global__ __launch_bounds__(256)
void mix_kernel(const float* __restrict__ x, float* __restrict__ out2)
{
    __shared__ float sx [2048];   // x tile, then reused for relu(ln(out1))
    __shared__ float sM [4096];   // M[c][o] : c*64+o
    __shared__ float sSt[4096];   // S transposed: [p][q] = p*128+q
    __shared__ float red[32];

    const int tid = threadIdx.x;
    const int blk = blockIdx.x;        // n*4 + g
    const int n = blk >> 2;
    const int g = blk & 3;

    const float* prow = g_params + (size_t)n * NCOLS + (size_t)g * 8192;
    const float* xrow = x + (size_t)blk * 2048;

    for (int i = tid; i < 512; i += 256)
        reinterpret_cast<float4*>(sx)[i] = reinterpret_cast<const float4*>(xrow)[i];
    for (int i = tid; i < 1024; i += 256)
        reinterpret_cast<float4*>(sM)[i] = reinterpret_cast<const float4*>(prow)[i];
    // transpose S on load: S[q][p] at prow[4096 + q*32 + p] -> sSt[p*128+q]
    for (int i = tid; i < 4096; i += 256) {
        int p = i >> 7, q = i & 127;
        sSt[i] = prow[4096 + q * 32 + p];
    }
    __syncthreads();

    // ---------- phase 1: out1[p][o] = sum_c x[p][c] * M[c][o] ----------
    const int pt = (tid >> 4) * 2;     // p tile (2 rows)
    const int ot = (tid & 15) * 4;     // o tile (4 cols)
    float a1[2][4];
    #pragma unroll
    for (int i = 0; i < 2; i++)
        #pragma unroll
        for (int j = 0; j < 4; j++) a1[i][j] = 0.f;

    #pragma unroll 4
    for (int c0 = 0; c0 < 64; c0 += 4) {
        float4 x0v = *reinterpret_cast<const float4*>(&sx[pt * 64 + c0]);
        float4 x1v = *reinterpret_cast<const float4*>(&sx[pt * 64 + 64 + c0]);
        float xa0[4] = {x0v.x, x0v.y, x0v.z, x0v.w};
        float xa1[4] = {x1v.x, x1v.y, x1v.z, x1v.w};
        #pragma unroll
        for (int cc = 0; cc < 4; cc++) {
            float4 m = *reinterpret_cast<const float4*>(&sM[(c0 + cc) * 64 + ot]);
            a1[0][0] = fmaf(xa0[cc], m.x, a1[0][0]);
            a1[0][1] = fmaf(xa0[cc], m.y, a1[0][1]);
            a1[0][2] = fmaf(xa0[cc], m.z, a1[0][2]);
            a1[0][3] = fmaf(xa0[cc], m.w, a1[0][3]);
            a1[1][0] = fmaf(xa1[cc], m.x, a1[1][0]);
            a1[1][1] = fmaf(xa1[cc], m.y, a1[1][1]);
            a1[1][2] = fmaf(xa1[cc], m.z, a1[1][2]);
            a1[1][3] = fmaf(xa1[cc], m.w, a1[1][3]);
        }
    }

    float s = 0.f, ss = 0.f;
    #pragma unroll
    for (int i = 0; i < 2; i++)
        #pragma unroll
        for (int j = 0; j < 4; j++) { s += a1[i][j]; ss += a1[i][j] * a1[i][j]; }
    float2 r = block_reduce2(s, ss, red);   // includes barriers: safe to overwrite sx after
    float mu = r.x * (1.f / 2048.f);
    float rs = rsqrtf(r.y * (1.f / 2048.f) - mu * mu + LN_EPS);
    #pragma unroll
    for (int i = 0; i < 2; i++)
        #pragma unroll
        for (int j = 0; j < 4; j++)
            sx[(pt + i) * 64 + ot + j] = fmaxf((a1[i][j] - mu) * rs, 0.f);
    __syncthreads();

    // ---------- phase 2: out2[q][o] = sum_p S[q][p] * out1[p][o] ----------
    const int qt = (tid >> 3) * 4;     // q tile (4 rows)
    const int o2 = (tid & 7) * 8;      // o tile (8 cols)
    float a2[4][8];
    #pragma unroll
    for (int i = 0; i < 4; i++)
        #pragma unroll
        for (int j = 0; j < 8; j++) a2[i][j] = 0.f;

    #pragma unroll 4
    for (int p = 0; p < 32; p++) {
        float4 sv = *reinterpret_cast<const float4*>(&sSt[p * 128 + qt]);
        float4 u0 = *reinterpret_cast<const float4*>(&sx[p * 64 + o2]);
        float4 u1 = *reinterpret_cast<const float4*>(&sx[p * 64 + o2 + 4]);
        float sa[4] = {sv.x, sv.y, sv.z, sv.w};
        float ua[8] = {u0.x, u0.y, u0.z, u0.w, u1.x, u1.y, u1.z, u1.w};
        #pragma unroll
        for (int i = 0; i < 4; i++)
            #pragma unroll
            for (int j = 0; j < 8; j++)
                a2[i][j] = fmaf(sa[i], ua[j], a2[i][j]);
    }

    s = 0.f; ss = 0.f;
    #pragma unroll
    for (int i = 0; i < 4; i++)
        #pragma unroll
        for (int j = 0; j < 8; j++) { s += a2[i][j]; ss += a2[i][j] * a2[i][j]; }
    r = block_reduce2(s, ss, red);
    mu = r.x * (1.f / 8192.f);
    rs = rsqrtf(r.y * (1.f / 8192.f) - mu * mu + LN_EPS);

    float* orow = out2 + (size_t)n * NCOLS + (size_t)g * 8192;
    #pragma unroll
    for (int i = 0; i < 4; i++) {
        int q = qt + i;
        float4 w0, w1;
        w0.x = fmaxf((a2[i][0] - mu) * rs, 0.f);
        w0.y = fmaxf((a2[i][1] - mu) * rs, 0.f);
        w0.z = fmaxf((a2[i][2] - mu) * rs, 0.f);
        w0.w = fmaxf((a2[i][3] - mu) * rs, 0.f);
        w1.x = fmaxf((a2[i][4] - mu) * rs, 0.f);
        w1.y = fmaxf((a2[i][5] - mu) * rs, 0.f);
        w1.z = fmaxf((a2[i][6] - mu) * rs, 0.f);
        w1.w = fmaxf((a2[i][7] - mu) * rs, 0.f);
        *reinterpret_cast<float4*>(&orow[q * 64 + o2])     = w0;
        *reinterpret_cast<float4*>(&orow[q * 64 + o2 + 4]) = w1;
    }
}

// =====================================================================
// combine: out = query + bo + sum_z partials
// =====================================================================
__global__ void combine_k(const float* __restrict__ query, const float* __restrict__ bo,
                          float* __restrict__ out)
{
    int i = blockIdx.x * 256 + threadIdx.x;
    if (i >= NTOK * 256) return;
    float s = query[i] + bo[i & 255];
    #pragma unroll
    for (int z = 0; z < SPLITK; z++)
        s += g_part[(size_t)z * (NTOK * 256) + i];
    out[i] = s;
}

// =====================================================================
extern "C" void kernel_launch(void* const* d_in, const int* in_sizes, int n_in,
                              void* d_out, int out_size)
{
    (void)in_sizes; (void)n_in; (void)out_size;
    const float* x  = (const float*)d_in[0];
    const float* q  = (const float*)d_in[1];
    const float* Wp = (const float*)d_in[2];
    const float* bp = (const float*)d_in[3];
    const float* Wo = (const float*)d_in[4];
    const float* bo = (const float*)d_in[5];
    float* out = (float*)d_out;

    float *pparams, *pout2, *ppart;
    cudaGetSymbolAddress((void**)&pparams, g_params);
    cudaGetSymbolAddress((void**)&pout2,  g_out2);
    cudaGetSymbolAddress((void**)&ppart,  g_part);

    // 1) params = query @ Wp + bp   [3600,256]x[256,32768]
    dim3 g1(NCOLS / 128, (NTOK + 127) / 128, 1);
    sgemm128<<<g1, 256>>>(q, Wp, bp, pparams, NTOK, NCOLS, 256, 0);

    // 2) fused adaptive mixing per (token, group)
    mix_kernel<<<NTOK * 4, 256>>>(x, pout2);

    // 3) out2 @ Wo  (split-K deterministic partials)
    dim3 g3(256 / 128, (NTOK + 127) / 128, SPLITK);
    sgemm128<<<g3, 256>>>(pout2, Wo, nullptr, ppart, NTOK, 256, NCOLS, KCHUNK);

    // 4) residual + bias + partial sum
    combine_k<<<(NTOK * 256 + 255) / 256, 256>>>(q, bo, out);
}

// round 10
// speedup vs baseline: 1.1321x; 1.1321x over previous
#include <cuda_runtime.h>
#include <cuda_bf16.h>
#include <cstdint>

// ---------------- problem constants ----------------
#define NTOK   3600            // B*Q
#define NCOLS  32768           // G * TOTAL
#define SPLITK 16
#define KCHUNK (NCOLS / SPLITK)   // 2048
#define LN_EPS 1e-5f

// ---------------- scratch (device globals; no allocations allowed) -------
__device__ float g_params[(size_t)NTOK * NCOLS];          // 472 MB
__device__ float g_out2[(size_t)NTOK * NCOLS];            // 472 MB
__device__ float g_part[(size_t)SPLITK * NTOK * 256];     // 59 MB

__device__ __forceinline__ uint32_t saddr(const void* p) {
    return (uint32_t)__cvta_generic_to_shared(p);
}

#define MMA_BF16(c, a, b)                                                          \
    asm volatile(                                                                  \
        "mma.sync.aligned.m16n8k16.row.col.f32.bf16.bf16.f32 "                     \
        "{%0,%1,%2,%3},{%4,%5,%6,%7},{%8,%9},{%0,%1,%2,%3};"                       \
        : "+f"((c)[0]), "+f"((c)[1]), "+f"((c)[2]), "+f"((c)[3])                   \
        : "r"((a)[0]), "r"((a)[1]), "r"((a)[2]), "r"((a)[3]),                      \
          "r"((b)[0]), "r"((b)[1]))

#define LDSM_X4(r, addr)                                                           \
    asm volatile("ldmatrix.sync.aligned.m8n8.x4.shared.b16 {%0,%1,%2,%3},[%4];"    \
                 : "=r"((r)[0]), "=r"((r)[1]), "=r"((r)[2]), "=r"((r)[3])          \
                 : "r"(addr))

#define LDSM_X2(r, addr)                                                           \
    asm volatile("ldmatrix.sync.aligned.m8n8.x2.shared.b16 {%0,%1},[%2];"          \
                 : "=r"((r)[0]), "=r"((r)[1])                                      \
                 : "r"(addr))

// =====================================================================
// Tensor-core GEMM with bf16 hi/lo splitting (3-pass, fp32 accumulate).
// C[M,N] = A[M,K] @ B[K,N] (+ bias over N).  fp32 in, fp32 out.
// 128x128 block tile, BK=32, 256 threads (8 warps, warp tile 64x32).
// kChunk > 0: split-K partials at C + z*M*N (no bias).
// =====================================================================
__global__ __launch_bounds__(256)
void gemm_tc(const float* __restrict__ A, const float* __restrict__ B,
             const float* __restrict__ bias, float* __restrict__ C,
             int M, int N, int K, int kChunk)
{
    __shared__ __align__(16) __nv_bfloat16 Ah[128][40];
    __shared__ __align__(16) __nv_bfloat16 Al[128][40];
    __shared__ __align__(16) __nv_bfloat16 Bh[128][40];   // transposed: [n][k]
    __shared__ __align__(16) __nv_bfloat16 Bl[128][40];

    const int tid  = threadIdx.x;
    const int lane = tid & 31;
    const int warp = tid >> 5;
    const int wm   = warp >> 2;        // 0..1  (64 rows each)
    const int wn   = warp & 3;         // 0..3  (32 cols each)

    const int brow = blockIdx.y * 128;
    const int bcol = blockIdx.x * 128;

    int kStart = 0, kEnd = K;
    float* Cp = C;
    if (kChunk > 0) {
        kStart = blockIdx.z * kChunk;
        kEnd   = kStart + kChunk;
        Cp     = C + (size_t)blockIdx.z * (size_t)M * (size_t)N;
    }

    float acc[4][4][4];
    #pragma unroll
    for (int mt = 0; mt < 4; mt++)
        #pragma unroll
        for (int nt = 0; nt < 4; nt++)
            #pragma unroll
            for (int r = 0; r < 4; r++) acc[mt][nt][r] = 0.f;

    float4 pA[4], pB[4];

    // ---- global prefetch (A: 128x32 fp32, B: 32x128 fp32) ----
    auto loadAB = [&](int k0) {
        #pragma unroll
        for (int it = 0; it < 4; it++) {
            int r  = (tid >> 3) + it * 32;
            int c  = (tid & 7) * 4;
            int gr = brow + r;
            float4 v = make_float4(0.f, 0.f, 0.f, 0.f);
            if (gr < M)
                v = *reinterpret_cast<const float4*>(A + (size_t)gr * K + k0 + c);
            pA[it] = v;
        }
        #pragma unroll
        for (int it = 0; it < 4; it++) {
            int kr = (tid >> 5) + it * 8;
            int c  = (tid & 31) * 4;
            pB[it] = *reinterpret_cast<const float4*>(B + (size_t)(k0 + kr) * N + bcol + c);
        }
    };

    // ---- convert fp32 regs -> hi/lo bf16 smem ----
    auto stage = [&]() {
        #pragma unroll
        for (int it = 0; it < 4; it++) {
            int r = (tid >> 3) + it * 32;
            int c = (tid & 7) * 4;
            float v[4] = {pA[it].x, pA[it].y, pA[it].z, pA[it].w};
            #pragma unroll
            for (int j = 0; j < 4; j += 2) {
                __nv_bfloat16 h0 = __float2bfloat16(v[j]);
                __nv_bfloat16 h1 = __float2bfloat16(v[j + 1]);
                __nv_bfloat16 l0 = __float2bfloat16(v[j] - __bfloat162float(h0));
                __nv_bfloat16 l1 = __float2bfloat16(v[j + 1] - __bfloat162float(h1));
                *reinterpret_cast<__nv_bfloat162*>(&Ah[r][c + j]) = __halves2bfloat162(h0, h1);
                *reinterpret_cast<__nv_bfloat162*>(&Al[r][c + j]) = __halves2bfloat162(l0, l1);
            }
        }
        #pragma unroll
        for (int it = 0; it < 4; it++) {
            int kr = (tid >> 5) + it * 8;
            int c  = (tid & 31) * 4;
            float v[4] = {pB[it].x, pB[it].y, pB[it].z, pB[it].w};
            #pragma unroll
            for (int j = 0; j < 4; j++) {
                __nv_bfloat16 h = __float2bfloat16(v[j]);
                __nv_bfloat16 l = __float2bfloat16(v[j] - __bfloat162float(h));
                Bh[c + j][kr] = h;
                Bl[c + j][kr] = l;
            }
        }
    };

    // ---- tensor-core compute over current smem tile ----
    auto compute = [&]() {
        #pragma unroll
        for (int kh = 0; kh < 2; kh++) {
            const int k16 = kh * 16;
            uint32_t ah[4][4], al[4][4], bh[4][2], bl[4][2];
            #pragma unroll
            for (int nt = 0; nt < 4; nt++) {
                int rl   = lane & 15;
                int nrow = wn * 32 + nt * 8 + (rl & 7);
                int ncol = k16 + ((rl >> 3) << 3);
                LDSM_X2(bh[nt], saddr(&Bh[nrow][ncol]));
                LDSM_X2(bl[nt], saddr(&Bl[nrow][ncol]));
            }
            #pragma unroll
            for (int mt = 0; mt < 4; mt++) {
                int arow = wm * 64 + mt * 16 + (lane & 15);
                int acol = k16 + ((lane >> 4) << 3);
                LDSM_X4(ah[mt], saddr(&Ah[arow][acol]));
                LDSM_X4(al[mt], saddr(&Al[arow][acol]));
            }
            #pragma unroll
            for (int mt = 0; mt < 4; mt++)
                #pragma unroll
                for (int nt = 0; nt < 4; nt++) {
                    MMA_BF16(acc[mt][nt], ah[mt], bh[nt]);
                    MMA_BF16(acc[mt][nt], ah[mt], bl[nt]);
                    MMA_BF16(acc[mt][nt], al[mt], bh[nt]);
                }
        }
    };

    loadAB(kStart);
    stage();
    __syncthreads();

    for (int k0 = kStart; k0 < kEnd; k0 += 32) {
        const bool more = (k0 + 32) < kEnd;
        if (more) loadAB(k0 + 32);     // LDGs issue early, consumed after compute
        compute();
        if (more) {
            __syncthreads();
            stage();
            __syncthreads();
        }
    }

    // ---- epilogue ----
    #pragma unroll
    for (int mt = 0; mt < 4; mt++) {
        #pragma unroll
        for (int nt = 0; nt < 4; nt++) {
            int r = brow + wm * 64 + mt * 16 + (lane >> 2);
            int c = bcol + wn * 32 + nt * 8 + (lane & 3) * 2;
            float b0 = 0.f, b1 = 0.f;
            if (bias) { b0 = bias[c]; b1 = bias[c + 1]; }
            if (r < M) {
                float2 v = make_float2(acc[mt][nt][0] + b0, acc[mt][nt][1] + b1);
                *reinterpret_cast<float2*>(Cp + (size_t)r * N + c) = v;
            }
            if (r + 8 < M) {
                float2 v = make_float2(acc[mt][nt][2] + b0, acc[mt][nt][3] + b1);
                *reinterpret_cast<float2*>(Cp + (size_t)(r + 8) * N + c) = v;
            }
        }
    }
}

// =====================================================================
// block-wide (sum, sumsq) reduction, 256 threads
// =====================================================================
__device__ __forceinline__ float2 block_reduce2(float s, float q, float* red)
{
    #pragma unroll
    for (int off = 16; off > 0; off >>= 1) {
        s += __shfl_down_sync(0xffffffffu, s, off);
        q += __shfl_down_sync(0xffffffffu, q, off);
    }
    const int w = threadIdx.x >> 5;
    if ((threadIdx.x & 31) == 0) { red[w] = s; red[8 + w] = q; }
    __syncthreads();
    if (threadIdx.x < 32) {
        s = (threadIdx.x < 8) ? red[threadIdx.x]     : 0.f;
        q = (threadIdx.x < 8) ? red[8 + threadIdx.x] : 0.f;
        #pragma unroll
        for (int off = 4; off > 0; off >>= 1) {
            s += __shfl_down_sync(0xffffffffu, s, off);
            q += __shfl_down_sync(0xffffffffu, q, off);
        }
        if (threadIdx.x == 0) { red[0] = s; red[1] = q; }
    }
    __syncthreads();
    return make_float2(red[0], red[1]);
}

// =====================================================================
// Fused per-(token,group) kernel:
//   out1 = relu(LN2d( x[n,g] (32x64) @ M[n,g] (64x64) ))      [in SMEM]
//   out2 = relu(LN2d( S[n,g] (128x32) @ out1 (32x64) ))       -> global
// One block per (n,g). 256 threads.
// =====================================================================
__global__ __launch_bounds__(256)
void mix_kernel(const float* __restrict__ x, float* __restrict__ out2)
{
    __shared__ float sx [2048];   // x tile, then reused for relu(ln(out1))
    __shared__ float sM [4096];   // M[c][o] : c*64+o
    __shared__ float sSt[4096];   // S transposed: [p][q] = p*128+q
    __shared__ float red[32];

    const int tid = threadIdx.x;
    const int blk = blockIdx.x;        // n*4 + g
    const int n = blk >> 2;
    const int g = blk & 3;

    const float* prow = g_params + (size_t)n * NCOLS + (size_t)g * 8192;
    const float* xrow = x + (size_t)blk * 2048;

    for (int i = tid; i < 512; i += 256)
        reinterpret_cast<float4*>(sx)[i] = reinterpret_cast<const float4*>(xrow)[i];
    for (int i = tid; i < 1024; i += 256)
        reinterpret_cast<float4*>(sM)[i] = reinterpret_cast<const float4*>(prow)[i];
    for (int i = tid; i < 4096; i += 256) {
        int p = i >> 7, q = i & 127;
        sSt[i] = prow[4096 + q * 32 + p];
    }
    __syncthreads();

    // ---------- phase 1: out1[p][o] = sum_c x[p][c] * M[c][o] ----------
    const int pt = (tid >> 4) * 2;
    const int ot = (tid & 15) * 4;
    float a1[2][4];
    #pragma unroll
    for (int i = 0; i < 2; i++)
        #pragma unroll
        for (int j = 0; j < 4; j++) a1[i][j] = 0.f;

    #pragma unroll 4
    for (int c0 = 0; c0 < 64; c0 += 4) {
        float4 x0v = *reinterpret_cast<const float4*>(&sx[pt * 64 + c0]);
        float4 x1v = *reinterpret_cast<const float4*>(&sx[pt * 64 + 64 + c0]);
        float xa0[4] = {x0v.x, x0v.y, x0v.z, x0v.w};
        float xa1[4] = {x1v.x, x1v.y, x1v.z, x1v.w};
        #pragma unroll
        for (int cc = 0; cc < 4; cc++) {
            float4 m = *reinterpret_cast<const float4*>(&sM[(c0 + cc) * 64 + ot]);
            a1[0][0] = fmaf(xa0[cc], m.x, a1[0][0]);
            a1[0][1] = fmaf(xa0[cc], m.y, a1[0][1]);
            a1[0][2] = fmaf(xa0[cc], m.z, a1[0][2]);
            a1[0][3] = fmaf(xa0[cc], m.w, a1[0][3]);
            a1[1][0] = fmaf(xa1[cc], m.x, a1[1][0]);
            a1[1][1] = fmaf(xa1[cc], m.y, a1[1][1]);
            a1[1][2] = fmaf(xa1[cc], m.z, a1[1][2]);
            a1[1][3] = fmaf(xa1[cc], m.w, a1[1][3]);
        }
    }

    float s = 0.f, ss = 0.f;
    #pragma unroll
    for (int i = 0; i < 2; i++)
        #pragma unroll
        for (int j = 0; j < 4; j++) { s += a1[i][j]; ss += a1[i][j] * a1[i][j]; }
    float2 r = block_reduce2(s, ss, red);
    float mu = r.x * (1.f / 2048.f);
    float rs = rsqrtf(r.y * (1.f / 2048.f) - mu * mu + LN_EPS);
    #pragma unroll
    for (int i = 0; i < 2; i++)
        #pragma unroll
        for (int j = 0; j < 4; j++)
            sx[(pt + i) * 64 + ot + j] = fmaxf((a1[i][j] - mu) * rs, 0.f);
    __syncthreads();

    // ---------- phase 2: out2[q][o] = sum_p S[q][p] * out1[p][o] ----------
    const int qt = (tid >> 3) * 4;
    const int o2 = (tid & 7) * 8;
    float a2[4][8];
    #pragma unroll
    for (int i = 0; i < 4; i++)
        #pragma unroll
        for (int j = 0; j < 8; j++) a2[i][j] = 0.f;

    #pragma unroll 4
    for (int p = 0; p < 32; p++) {
        float4 sv = *reinterpret_cast<const float4*>(&sSt[p * 128 + qt]);
        float4 u0 = *reinterpret_cast<const float4*>(&sx[p * 64 + o2]);
        float4 u1 = *reinterpret_cast<const float4*>(&sx[p * 64 + o2 + 4]);
        float sa[4] = {sv.x, sv.y, sv.z, sv.w};
        float ua[8] = {u0.x, u0.y, u0.z, u0.w, u1.x, u1.y, u1.z, u1.w};
        #pragma unroll
        for (int i = 0; i < 4; i++)
            #pragma unroll
            for (int j = 0; j < 8; j++)
                a2[i][j] = fmaf(sa[i], ua[j], a2[i][j]);
    }

    s = 0.f; ss = 0.f;
    #pragma unroll
    for (int i = 0; i < 4; i++)
        #pragma unroll
        for (int j = 0; j < 8; j++) { s += a2[i][j]; ss += a2[i][j] * a2[i][j]; }
    r = block_reduce2(s, ss, red);
    mu = r.x * (1.f / 8192.f);
    rs = rsqrtf(r.y * (1.f / 8192.f) - mu * mu + LN_EPS);

    float* orow = out2 + (size_t)n * NCOLS + (size_t)g * 8192;
    #pragma unroll
    for (int i = 0; i < 4; i++) {
        int q = qt + i;
        float4 w0, w1;
        w0.x = fmaxf((a2[i][0] - mu) * rs, 0.f);
        w0.y = fmaxf((a2[i][1] - mu) * rs, 0.f);
        w0.z = fmaxf((a2[i][2] - mu) * rs, 0.f);
        w0.w = fmaxf((a2[i][3] - mu) * rs, 0.f);
        w1.x = fmaxf((a2[i][4] - mu) * rs, 0.f);
        w1.y = fmaxf((a2[i][5] - mu) * rs, 0.f);
        w1.z = fmaxf((a2[i][6] - mu) * rs, 0.f);
        w1.w = fmaxf((a2[i][7] - mu) * rs, 0.f);
        *reinterpret_cast<float4*>(&orow[q * 64 + o2])     = w0;
        *reinterpret_cast<float4*>(&orow[q * 64 + o2 + 4]) = w1;
    }
}

// =====================================================================
// combine: out = query + bo + sum_z partials
// =====================================================================
__global__ void combine_k(const float* __restrict__ query, const float* __restrict__ bo,
                          float* __restrict__ out)
{
    int i = blockIdx.x * 256 + threadIdx.x;
    if (i >= NTOK * 256) return;
    float s = query[i] + bo[i & 255];
    #pragma unroll
    for (int z = 0; z < SPLITK; z++)
        s += g_part[(size_t)z * (NTOK * 256) + i];
    out[i] = s;
}

// =====================================================================
extern "C" void kernel_launch(void* const* d_in, const int* in_sizes, int n_in,
                              void* d_out, int out_size)
{
    (void)in_sizes; (void)n_in; (void)out_size;
    const float* x  = (const float*)d_in[0];
    const float* q  = (const float*)d_in[1];
    const float* Wp = (const float*)d_in[2];
    const float* bp = (const float*)d_in[3];
    const float* Wo = (const float*)d_in[4];
    const float* bo = (const float*)d_in[5];
    float* out = (float*)d_out;

    float *pparams, *pout2, *ppart;
    cudaGetSymbolAddress((void**)&pparams, g_params);
    cudaGetSymbolAddress((void**)&pout2,  g_out2);
    cudaGetSymbolAddress((void**)&ppart,  g_part);

    // 1) params = query @ Wp + bp   [3600,256]x[256,32768]  (tensor cores)
    dim3 g1(NCOLS / 128, (NTOK + 127) / 128, 1);
    gemm_tc<<<g1, 256>>>(q, Wp, bp, pparams, NTOK, NCOLS, 256, 0);

    // 2) fused adaptive mixing per (token, group)
    mix_kernel<<<NTOK * 4, 256>>>(x, pout2);

    // 3) out2 @ Wo  (tensor cores, deterministic split-K partials)
    dim3 g3(256 / 128, (NTOK + 127) / 128, SPLITK);
    gemm_tc<<<g3, 256>>>(pout2, Wo, nullptr, ppart, NTOK, 256, NCOLS, KCHUNK);

    // 4) residual + bias + partial sum
    combine_k<<<(NTOK * 256 + 255) / 256, 256>>>(q, bo, out);
}

// round 12
// speedup vs baseline: 2.2713x; 2.0062x over previous
#include <cuda_runtime.h>
#include <cuda_bf16.h>
#include <cstdint>

// ---------------- problem constants ----------------
#define NTOK   3600            // B*Q
#define NCOLS  32768           // G * TOTAL
#define SPLITK 16
#define KCHUNK (NCOLS / SPLITK)   // 2048
#define LN_EPS 1e-5f

// ---------------- scratch (device globals; no allocations allowed) -------
__device__ float g_params[(size_t)NTOK * NCOLS];                 // 472 MB
__device__ __nv_bfloat16 g_o2h[(size_t)NTOK * NCOLS];            // 236 MB
__device__ __nv_bfloat16 g_o2l[(size_t)NTOK * NCOLS];            // 236 MB
__device__ float g_part[(size_t)SPLITK * NTOK * 256];            // 59 MB
__device__ __nv_bfloat16 g_Wph[(size_t)256 * NCOLS];
__device__ __nv_bfloat16 g_Wpl[(size_t)256 * NCOLS];
__device__ __nv_bfloat16 g_Woh[(size_t)NCOLS * 256];
__device__ __nv_bfloat16 g_Wol[(size_t)NCOLS * 256];
__device__ __nv_bfloat16 g_qh[(size_t)NTOK * 256];
__device__ __nv_bfloat16 g_ql[(size_t)NTOK * 256];

__device__ __forceinline__ uint32_t saddr(const void* p) {
    return (uint32_t)__cvta_generic_to_shared(p);
}

#define MMA_BF16(c, a, b)                                                          \
    asm volatile(                                                                  \
        "mma.sync.aligned.m16n8k16.row.col.f32.bf16.bf16.f32 "                     \
        "{%0,%1,%2,%3},{%4,%5,%6,%7},{%8,%9},{%0,%1,%2,%3};"                       \
        : "+f"((c)[0]), "+f"((c)[1]), "+f"((c)[2]), "+f"((c)[3])                   \
        : "r"((a)[0]), "r"((a)[1]), "r"((a)[2]), "r"((a)[3]),                      \
          "r"((b)[0]), "r"((b)[1]))

#define LDSM_X4(r, addr)                                                           \
    asm volatile("ldmatrix.sync.aligned.m8n8.x4.shared.b16 {%0,%1,%2,%3},[%4];"    \
                 : "=r"((r)[0]), "=r"((r)[1]), "=r"((r)[2]), "=r"((r)[3])          \
                 : "r"(addr))

#define LDSM_X2T(r, addr)                                                          \
    asm volatile("ldmatrix.sync.aligned.m8n8.x2.trans.shared.b16 {%0,%1},[%2];"    \
                 : "=r"((r)[0]), "=r"((r)[1])                                      \
                 : "r"(addr))

#define CP16(dst, src)                                                             \
    asm volatile("cp.async.cg.shared.global [%0],[%1],16;\n" :: "r"(dst), "l"(src))
#define CP16Z(dst, src, p)                                                         \
    asm volatile("{\n .reg .pred q;\n setp.ne.b32 q,%2,0;\n"                       \
                 " @q  cp.async.cg.shared.global [%0],[%1],16;\n"                  \
                 " @!q cp.async.cg.shared.global [%0],[%1],16,0;\n}\n"             \
                 :: "r"(dst), "l"(src), "r"((int)(p)))
#define CP_COMMIT() asm volatile("cp.async.commit_group;\n")
#define CP_WAIT(n)  asm volatile("cp.async.wait_group %0;\n" :: "n"(n))

// =====================================================================
// cvt_split: fp32 -> (hi, lo) bf16, vectorized by 4
// =====================================================================
__global__ void cvt_split(const float* __restrict__ in, __nv_bfloat16* __restrict__ h,
                          __nv_bfloat16* __restrict__ l, int n4)
{
    int i = blockIdx.x * 256 + threadIdx.x;
    if (i >= n4) return;
    float4 v = reinterpret_cast<const float4*>(in)[i];
    __nv_bfloat16 h0 = __float2bfloat16(v.x), h1 = __float2bfloat16(v.y);
    __nv_bfloat16 h2 = __float2bfloat16(v.z), h3 = __float2bfloat16(v.w);
    __nv_bfloat16 l0 = __float2bfloat16(v.x - __bfloat162float(h0));
    __nv_bfloat16 l1 = __float2bfloat16(v.y - __bfloat162float(h1));
    __nv_bfloat16 l2 = __float2bfloat16(v.z - __bfloat162float(h2));
    __nv_bfloat16 l3 = __float2bfloat16(v.w - __bfloat162float(h3));
    reinterpret_cast<__nv_bfloat162*>(h)[2 * i]     = __halves2bfloat162(h0, h1);
    reinterpret_cast<__nv_bfloat162*>(h)[2 * i + 1] = __halves2bfloat162(h2, h3);
    reinterpret_cast<__nv_bfloat162*>(l)[2 * i]     = __halves2bfloat162(l0, l1);
    reinterpret_cast<__nv_bfloat162*>(l)[2 * i + 1] = __halves2bfloat162(l2, l3);
}

// =====================================================================
// Tensor-core GEMM, bf16 hi/lo inputs (3-pass, fp32 accumulate).
// C[M,N] = A[M,K] @ B[K,N] (+ bias).  A: [M,K] bf16 h/l,  B: [K,N] bf16 h/l.
// 128x128x32 block tile, 256 threads (8 warps, warp tile 64x32).
// cp.async double-buffered pipeline; ldmatrix (A) + ldmatrix.trans (B).
// kChunk > 0: split-K partials at C + z*M*N (no bias).
// =====================================================================
__global__ __launch_bounds__(256)
void gemm_bf(const __nv_bfloat16* __restrict__ Ahg, const __nv_bfloat16* __restrict__ Alg,
             const __nv_bfloat16* __restrict__ Bhg, const __nv_bfloat16* __restrict__ Blg,
             const float* __restrict__ bias, float* __restrict__ C,
             int M, int N, int K, int kChunk)
{
    // padded strides: A rows 40 elems (80B -> 20-bank stagger), B rows 136 (4-bank stagger)
    extern __shared__ __nv_bfloat16 sm[];
    __nv_bfloat16* sAh = sm;                 // [2][128*40]
    __nv_bfloat16* sAl = sAh + 2 * 5120;
    __nv_bfloat16* sBh = sAl + 2 * 5120;     // [2][32*136]
    __nv_bfloat16* sBl = sBh + 2 * 4352;

    const int tid  = threadIdx.x;
    const int lane = tid & 31;
    const int warp = tid >> 5;
    const int wm   = warp >> 2;
    const int wn   = warp & 3;

    const int brow = blockIdx.y * 128;
    const int bcol = blockIdx.x * 128;

    int kStart = 0, kEnd = K;
    float* Cp = C;
    if (kChunk > 0) {
        kStart = blockIdx.z * kChunk;
        kEnd   = kStart + kChunk;
        Cp     = C + (size_t)blockIdx.z * (size_t)M * (size_t)N;
    }

    float acc[4][4][4];
    #pragma unroll
    for (int mt = 0; mt < 4; mt++)
        #pragma unroll
        for (int nt = 0; nt < 4; nt++)
            #pragma unroll
            for (int r = 0; r < 4; r++) acc[mt][nt][r] = 0.f;

    auto loadTile = [&](int buf, int k0) {
        // A: 128 rows x 32 k, 8 elems (16B) per cp; 512 chunks per matrix
        #pragma unroll
        for (int it = 0; it < 2; it++) {
            int i = tid + it * 256;
            int r = i >> 2, c = (i & 3) * 8;
            int gr = brow + r;
            int ok = gr < M;
            size_t so = (size_t)(ok ? gr : 0) * K + k0 + c;
            CP16Z(saddr(sAh + buf * 5120 + r * 40 + c), Ahg + so, ok);
            CP16Z(saddr(sAl + buf * 5120 + r * 40 + c), Alg + so, ok);
        }
        // B: 32 rows x 128 n
        #pragma unroll
        for (int it = 0; it < 2; it++) {
            int i = tid + it * 256;
            int r = i >> 4, c = (i & 15) * 8;
            size_t so = (size_t)(k0 + r) * N + bcol + c;
            CP16(saddr(sBh + buf * 4352 + r * 136 + c), Bhg + so);
            CP16(saddr(sBl + buf * 4352 + r * 136 + c), Blg + so);
        }
    };

    const int nTiles = (kEnd - kStart) / 32;
    loadTile(0, kStart);
    CP_COMMIT();

    for (int t = 0; t < nTiles; t++) {
        if (t + 1 < nTiles) {
            loadTile((t + 1) & 1, kStart + (t + 1) * 32);
            CP_COMMIT();
            CP_WAIT(1);
        } else {
            CP_WAIT(0);
        }
        __syncthreads();

        const int buf = t & 1;
        const __nv_bfloat16* A_h = sAh + buf * 5120;
        const __nv_bfloat16* A_l = sAl + buf * 5120;
        const __nv_bfloat16* B_h = sBh + buf * 4352;
        const __nv_bfloat16* B_l = sBl + buf * 4352;

        #pragma unroll
        for (int kh = 0; kh < 2; kh++) {
            const int k16 = kh * 16;
            uint32_t ah[4][4], al[4][4];
            #pragma unroll
            for (int mt = 0; mt < 4; mt++) {
                int arow = wm * 64 + mt * 16 + (lane & 15);
                int acol = k16 + ((lane >> 4) << 3);
                LDSM_X4(ah[mt], saddr(A_h + arow * 40 + acol));
                LDSM_X4(al[mt], saddr(A_l + arow * 40 + acol));
            }
            #pragma unroll
            for (int nt = 0; nt < 4; nt++) {
                uint32_t bh[2], bl[2];
                int krow = k16 + (lane & 15);
                int ncol = wn * 32 + nt * 8;
                LDSM_X2T(bh, saddr(B_h + krow * 136 + ncol));
                LDSM_X2T(bl, saddr(B_l + krow * 136 + ncol));
                #pragma unroll
                for (int mt = 0; mt < 4; mt++) {
                    MMA_BF16(acc[mt][nt], ah[mt], bh);
                    MMA_BF16(acc[mt][nt], ah[mt], bl);
                    MMA_BF16(acc[mt][nt], al[mt], bh);
                }
            }
        }
        __syncthreads();
    }

    // ---- epilogue ----
    #pragma unroll
    for (int mt = 0; mt < 4; mt++) {
        #pragma unroll
        for (int nt = 0; nt < 4; nt++) {
            int r = brow + wm * 64 + mt * 16 + (lane >> 2);
            int c = bcol + wn * 32 + nt * 8 + (lane & 3) * 2;
            float b0 = 0.f, b1 = 0.f;
            if (bias) { b0 = bias[c]; b1 = bias[c + 1]; }
            if (r < M) {
                float2 v = make_float2(acc[mt][nt][0] + b0, acc[mt][nt][1] + b1);
                *reinterpret_cast<float2*>(Cp + (size_t)r * N + c) = v;
            }
            if (r + 8 < M) {
                float2 v = make_float2(acc[mt][nt][2] + b0, acc[mt][nt][3] + b1);
                *reinterpret_cast<float2*>(Cp + (size_t)(r + 8) * N + c) = v;
            }
        }
    }
}

// =====================================================================
// block-wide (sum, sumsq) reduction, 256 threads
// =====================================================================
__device__ __forceinline__ float2 block_reduce2(float s, float q, float* red)
{
    #pragma unroll
    for (int off = 16; off > 0; off >>= 1) {
        s += __shfl_down_sync(0xffffffffu, s, off);
        q += __shfl_down_sync(0xffffffffu, q, off);
    }
    const int w = threadIdx.x >> 5;
    if ((threadIdx.x & 31) == 0) { red[w] = s; red[8 + w] = q; }
    __syncthreads();
    if (threadIdx.x < 32) {
        s = (threadIdx.x < 8) ? red[threadIdx.x]     : 0.f;
        q = (threadIdx.x < 8) ? red[8 + threadIdx.x] : 0.f;
        #pragma unroll
        for (int off = 4; off > 0; off >>= 1) {
            s += __shfl_down_sync(0xffffffffu, s, off);
            q += __shfl_down_sync(0xffffffffu, q, off);
        }
        if (threadIdx.x == 0) { red[0] = s; red[1] = q; }
    }
    __syncthreads();
    return make_float2(red[0], red[1]);
}

// =====================================================================
// Fused per-(token,group) kernel; out2 emitted as hi/lo bf16.
// =====================================================================
__global__ __launch_bounds__(256)
void mix_kernel(const float* __restrict__ x,
                __nv_bfloat16* __restrict__ o2h, __nv_bfloat16* __restrict__ o2l)
{
    __shared__ float sx [2048];
    __shared__ float sM [4096];
    __shared__ float sSt[4096];
    __shared__ float red[32];

    const int tid = threadIdx.x;
    const int blk = blockIdx.x;        // n*4 + g
    const int n = blk >> 2;
    const int g = blk & 3;

    const float* prow = g_params + (size_t)n * NCOLS + (size_t)g * 8192;
    const float* xrow = x + (size_t)blk * 2048;

    for (int i = tid; i < 512; i += 256)
        reinterpret_cast<float4*>(sx)[i] = reinterpret_cast<const float4*>(xrow)[i];
    for (int i = tid; i < 1024; i += 256)
        reinterpret_cast<float4*>(sM)[i] = reinterpret_cast<const float4*>(prow)[i];
    for (int i = tid; i < 4096; i += 256) {
        int p = i >> 7, q = i & 127;
        sSt[i] = prow[4096 + q * 32 + p];
    }
    __syncthreads();

    // ---------- phase 1 ----------
    const int pt = (tid >> 4) * 2;
    const int ot = (tid & 15) * 4;
    float a1[2][4];
    #pragma unroll
    for (int i = 0; i < 2; i++)
        #pragma unroll
        for (int j = 0; j < 4; j++) a1[i][j] = 0.f;

    #pragma unroll 4
    for (int c0 = 0; c0 < 64; c0 += 4) {
        float4 x0v = *reinterpret_cast<const float4*>(&sx[pt * 64 + c0]);
        float4 x1v = *reinterpret_cast<const float4*>(&sx[pt * 64 + 64 + c0]);
        float xa0[4] = {x0v.x, x0v.y, x0v.z, x0v.w};
        float xa1[4] = {x1v.x, x1v.y, x1v.z, x1v.w};
        #pragma unroll
        for (int cc = 0; cc < 4; cc++) {
            float4 m = *reinterpret_cast<const float4*>(&sM[(c0 + cc) * 64 + ot]);
            a1[0][0] = fmaf(xa0[cc], m.x, a1[0][0]);
            a1[0][1] = fmaf(xa0[cc], m.y, a1[0][1]);
            a1[0][2] = fmaf(xa0[cc], m.z, a1[0][2]);
            a1[0][3] = fmaf(xa0[cc], m.w, a1[0][3]);
            a1[1][0] = fmaf(xa1[cc], m.x, a1[1][0]);
            a1[1][1] = fmaf(xa1[cc], m.y, a1[1][1]);
            a1[1][2] = fmaf(xa1[cc], m.z, a1[1][2]);
            a1[1][3] = fmaf(xa1[cc], m.w, a1[1][3]);
        }
    }

    float s = 0.f, ss = 0.f;
    #pragma unroll
    for (int i = 0; i < 2; i++)
        #pragma unroll
        for (int j = 0; j < 4; j++) { s += a1[i][j]; ss += a1[i][j] * a1[i][j]; }
    float2 r = block_reduce2(s, ss, red);
    float mu = r.x * (1.f / 2048.f);
    float rs = rsqrtf(r.y * (1.f / 2048.f) - mu * mu + LN_EPS);
    #pragma unroll
    for (int i = 0; i < 2; i++)
        #pragma unroll
        for (int j = 0; j < 4; j++)
            sx[(pt + i) * 64 + ot + j] = fmaxf((a1[i][j] - mu) * rs, 0.f);
    __syncthreads();

    // ---------- phase 2 ----------
    const int qt = (tid >> 3) * 4;
    const int o2 = (tid & 7) * 8;
    float a2[4][8];
    #pragma unroll
    for (int i = 0; i < 4; i++)
        #pragma unroll
        for (int j = 0; j < 8; j++) a2[i][j] = 0.f;

    #pragma unroll 4
    for (int p = 0; p < 32; p++) {
        float4 sv = *reinterpret_cast<const float4*>(&sSt[p * 128 + qt]);
        float4 u0 = *reinterpret_cast<const float4*>(&sx[p * 64 + o2]);
        float4 u1 = *reinterpret_cast<const float4*>(&sx[p * 64 + o2 + 4]);
        float sa[4] = {sv.x, sv.y, sv.z, sv.w};
        float ua[8] = {u0.x, u0.y, u0.z, u0.w, u1.x, u1.y, u1.z, u1.w};
        #pragma unroll
        for (int i = 0; i < 4; i++)
            #pragma unroll
            for (int j = 0; j < 8; j++)
                a2[i][j] = fmaf(sa[i], ua[j], a2[i][j]);
    }

    s = 0.f; ss = 0.f;
    #pragma unroll
    for (int i = 0; i < 4; i++)
        #pragma unroll
        for (int j = 0; j < 8; j++) { s += a2[i][j]; ss += a2[i][j] * a2[i][j]; }
    r = block_reduce2(s, ss, red);
    mu = r.x * (1.f / 8192.f);
    rs = rsqrtf(r.y * (1.f / 8192.f) - mu * mu + LN_EPS);

    __nv_bfloat16* orh = o2h + (size_t)n * NCOLS + (size_t)g * 8192;
    __nv_bfloat16* orl = o2l + (size_t)n * NCOLS + (size_t)g * 8192;
    #pragma unroll
    for (int i = 0; i < 4; i++) {
        int q = qt + i;
        #pragma unroll
        for (int j = 0; j < 8; j += 2) {
            float v0 = fmaxf((a2[i][j]     - mu) * rs, 0.f);
            float v1 = fmaxf((a2[i][j + 1] - mu) * rs, 0.f);
            __nv_bfloat16 h0 = __float2bfloat16(v0), h1 = __float2bfloat16(v1);
            __nv_bfloat16 l0 = __float2bfloat16(v0 - __bfloat162float(h0));
            __nv_bfloat16 l1 = __float2bfloat16(v1 - __bfloat162float(h1));
            *reinterpret_cast<__nv_bfloat162*>(&orh[q * 64 + o2 + j]) = __halves2bfloat162(h0, h1);
            *reinterpret_cast<__nv_bfloat162*>(&orl[q * 64 + o2 + j]) = __halves2bfloat162(l0, l1);
        }
    }
}

// =====================================================================
// combine: out = query + bo + sum_z partials
// =====================================================================
__global__ void combine_k(const float* __restrict__ query, const float* __restrict__ bo,
                          float* __restrict__ out)
{
    int i = blockIdx.x * 256 + threadIdx.x;
    if (i >= NTOK * 256) return;
    float s = query[i] + bo[i & 255];
    #pragma unroll
    for (int z = 0; z < SPLITK; z++)
        s += g_part[(size_t)z * (NTOK * 256) + i];
    out[i] = s;
}

// =====================================================================
extern "C" void kernel_launch(void* const* d_in, const int* in_sizes, int n_in,
                              void* d_out, int out_size)
{
    (void)in_sizes; (void)n_in; (void)out_size;
    const float* x  = (const float*)d_in[0];
    const float* q  = (const float*)d_in[1];
    const float* Wp = (const float*)d_in[2];
    const float* bp = (const float*)d_in[3];
    const float* Wo = (const float*)d_in[4];
    const float* bo = (const float*)d_in[5];
    float* out = (float*)d_out;

    float *pparams, *ppart;
    __nv_bfloat16 *po2h, *po2l, *pWph, *pWpl, *pWoh, *pWol, *pqh, *pql;
    cudaGetSymbolAddress((void**)&pparams, g_params);
    cudaGetSymbolAddress((void**)&ppart,  g_part);
    cudaGetSymbolAddress((void**)&po2h, g_o2h);
    cudaGetSymbolAddress((void**)&po2l, g_o2l);
    cudaGetSymbolAddress((void**)&pWph, g_Wph);
    cudaGetSymbolAddress((void**)&pWpl, g_Wpl);
    cudaGetSymbolAddress((void**)&pWoh, g_Woh);
    cudaGetSymbolAddress((void**)&pWol, g_Wol);
    cudaGetSymbolAddress((void**)&pqh,  g_qh);
    cudaGetSymbolAddress((void**)&pql,  g_ql);

    const int SMEM = (2 * 5120 * 2 + 2 * 4352 * 2) * 2;   // 75776 B
    static bool attr_set = false;
    if (!attr_set) {
        cudaFuncSetAttribute(gemm_bf, cudaFuncAttributeMaxDynamicSharedMemorySize, SMEM);
        attr_set = true;
    }

    // 0) one-time-per-call hi/lo splits of the static operands
    cvt_split<<<(NTOK * 256 / 4 + 255) / 256, 256>>>(q, pqh, pql, NTOK * 256 / 4);
    cvt_split<<<(256 * NCOLS / 4 + 255) / 256, 256>>>(Wp, pWph, pWpl, 256 * NCOLS / 4);
    cvt_split<<<(NCOLS * 256 / 4 + 255) / 256, 256>>>(Wo, pWoh, pWol, NCOLS * 256 / 4);

    // 1) params = query @ Wp + bp   (pure tensor-core, cp.async pipeline)
    dim3 g1(NCOLS / 128, (NTOK + 127) / 128, 1);
    gemm_bf<<<g1, 256, SMEM>>>(pqh, pql, pWph, pWpl, bp, pparams, NTOK, NCOLS, 256, 0);

    // 2) fused adaptive mixing per (token, group), bf16 hi/lo out
    mix_kernel<<<NTOK * 4, 256>>>(x, po2h, po2l);

    // 3) out2 @ Wo  (tensor cores, deterministic split-K partials)
    dim3 g3(256 / 128, (NTOK + 127) / 128, SPLITK);
    gemm_bf<<<g3, 256, SMEM>>>(po2h, po2l, pWoh, pWol, nullptr, ppart, NTOK, 256, NCOLS, KCHUNK);

    // 4) residual + bias + partial sum
    combine_k<<<(NTOK * 256 + 255) / 256, 256>>>(q, bo, out);
}